// round 14
// baseline (speedup 1.0000x reference)
#include <cuda_runtime.h>

// out[b,o,h,w] = x[b,o,h,w] + bias[o],  bias[o] = -0.1f * sum_{c,kh,kw} |W2[o,c,kh,kw]|
//
// Derivation: adder2d outputs -sum|patch - w| <= 0 everywhere (strictly < 0 for
// continuous random inputs), so relu(adder2d(x, W1)) is exactly 0.0f everywhere.
// adder2d on an all-zero input (zero padding included) yields the per-channel
// constant -sum|W2[o]| at every spatial position. Hence
//   reference(x, W1, W2) == x - 0.1 * sum|W2[o,:,:,:]|.
//
// One block per (b,o) slab (4096 floats = 1024 float4); 256 threads x 4 float4 each,
// payload loads front-batched (MLP=4). Each WARP independently reduces the 576
// |W2[o]| values using 4 float4 + 2 scalar loads per lane (6 LSU ops instead of 18)
// + 5 butterfly shuffles — no __syncthreads, no shared memory, no cross-warp
// dependency on the critical path. W2 channel stride is 2304 B (16B-aligned).

__global__ __launch_bounds__(256) void fused_resblock_kernel(
    const float* __restrict__ x,
    const float* __restrict__ W2,
    float* __restrict__ out)
{
    const int t   = threadIdx.x;
    const int l   = t & 31;              // lane
    const int bid = blockIdx.x;          // slab index s = b*64 + o, 512 slabs
    const int o   = bid & 63;

    const float4* __restrict__ xv = reinterpret_cast<const float4*>(x)  + (size_t)bid * 1024;
    float4*       __restrict__ ov = reinterpret_cast<float4*>(out)      + (size_t)bid * 1024;

    // front-batch the payload loads (MLP=4) so they cover the bias critical path
    float4 v0 = xv[t];
    float4 v1 = xv[t + 256];
    float4 v2 = xv[t + 512];
    float4 v3 = xv[t + 768];

    // per-warp redundant bias reduction: sum |W2[o, 0:576]| (2.3 KB, cache-resident)
    const float*  w  = W2 + o * 576;                            // 16B-aligned
    const float4* w4 = reinterpret_cast<const float4*>(w);      // 128 float4 = first 512
    float s = 0.0f;
    #pragma unroll
    for (int i = 0; i < 4; i++) {                               // lanes cover [0,512)
        float4 q = __ldg(w4 + l + i * 32);
        s += fabsf(q.x) + fabsf(q.y) + fabsf(q.z) + fabsf(q.w);
    }
    s += fabsf(__ldg(w + 512 + l)) + fabsf(__ldg(w + 544 + l)); // tail [512,576)
    #pragma unroll
    for (int d = 16; d > 0; d >>= 1)
        s += __shfl_xor_sync(0xFFFFFFFFu, s, d);
    const float b = -0.1f * s;

    v0.x += b; v0.y += b; v0.z += b; v0.w += b;
    v1.x += b; v1.y += b; v1.z += b; v1.w += b;
    v2.x += b; v2.y += b; v2.z += b; v2.w += b;
    v3.x += b; v3.y += b; v3.z += b; v3.w += b;

    ov[t]       = v0;
    ov[t + 256] = v1;
    ov[t + 512] = v2;
    ov[t + 768] = v3;
}

extern "C" void kernel_launch(void* const* d_in, const int* in_sizes, int n_in,
                              void* d_out, int out_size) {
    const float* x  = (const float*)d_in[0];   // [8,64,64,64] float32
    // d_in[1] = W1 (unused: relu(adder2d(x, W1)) == 0 exactly)
    const float* W2 = (const float*)d_in[2];   // [64,64,3,3] float32
    float* out = (float*)d_out;

    const int slabs = out_size / 4096;         // 512 (b,o) slabs
    fused_resblock_kernel<<<slabs, 256>>>(x, W2, out);
}